// round 1
// baseline (speedup 1.0000x reference)
#include <cuda_runtime.h>

// Problem constants (fixed by the reference)
constexpr int H_   = 1024;
constexpr int W_   = 1024;
constexpr int FID_ = 100;
constexpr int NF_  = 8;
constexpr int NPTS = 1 << 20;
constexpr int KST  = 20;

// Pixel-interleaved accumulator: [H*W] x float4 (channels 0..3).
// 16 MB — lives in L2 for the whole run; __device__ global (no allocs allowed).
__device__ float4 g_acc[H_ * W_];

__global__ void zero_acc_kernel() {
    int i = blockIdx.x * blockDim.x + threadIdx.x;
    g_acc[i] = make_float4(0.f, 0.f, 0.f, 0.f);
}

__device__ __forceinline__ void red_add_v4(float4* addr, float4 v) {
    // sm_90+ vector float reduction: one L2 atomic op for all 4 channels.
    asm volatile("red.global.add.v4.f32 [%0], {%1,%2,%3,%4};"
                 :: "l"(addr), "f"(v.x), "f"(v.y), "f"(v.z), "f"(v.w)
                 : "memory");
}

__global__ __launch_bounds__(256) void flame_kernel(
    const float* __restrict__ points,      // [NPTS,3] (x,y,c)
    const int*   __restrict__ choices,     // [KST, NPTS]
    const float* __restrict__ A,           // [NF,2,2]
    const float* __restrict__ Bv,          // [NF,2]
    const float* __restrict__ fcol,        // [NF]
    const float* __restrict__ pal,         // [FID+1,4]
    const float* __restrict__ minv,        // [2]
    const float* __restrict__ rngv,        // [2]
    const int*   __restrict__ skipp)       // [1]
{
    __shared__ float4 sA[NF_];             // a00,a01,a10,a11
    __shared__ float2 sB[NF_];
    __shared__ float  sC[NF_];
    __shared__ float4 sP[FID_ + 1];

    const int t = threadIdx.x;
    if (t < NF_) {
        sA[t] = make_float4(A[4*t], A[4*t+1], A[4*t+2], A[4*t+3]);
        sB[t] = make_float2(Bv[2*t], Bv[2*t+1]);
        sC[t] = fcol[t];
    }
    for (int i = t; i <= FID_; i += blockDim.x)
        sP[i] = make_float4(pal[4*i], pal[4*i+1], pal[4*i+2], pal[4*i+3]);

    const float mnx = minv[0], mny = minv[1];
    const float rx  = rngv[0], ry  = rngv[1];
    const int skip  = skipp[0];
    __syncthreads();

    const int n = blockIdx.x * blockDim.x + t;
    float x = points[3*n + 0];
    float y = points[3*n + 1];
    float c = points[3*n + 2];

    #pragma unroll
    for (int k = 0; k < KST; k++) {
        const int idx   = choices[k * NPTS + n];
        const float4 a  = sA[idx];
        const float2 bb = sB[idx];
        const float nx = a.x * x + a.y * y + bb.x;
        const float ny = a.z * x + a.w * y + bb.y;
        c = 0.5f * (c + sC[idx]);
        x = nx; y = ny;

        if (k < skip) continue;

        // Matches XLA astype(int32): cvt.rzi.s32.f32 — truncate toward zero,
        // saturating, NaN -> 0. Note values in (-1,0) truncate to 0 and PASS
        // the bounds check, exactly as in the reference.
        const int xb = (int)((x - mnx) * rx);
        const int yb = (int)((y - mny) * ry);
        if ((unsigned)xb < (unsigned)W_ && (unsigned)yb < (unsigned)H_) {
            const float _c = c * (float)FID_;
            const float cf = floorf(_c);
            const float t1 = _c - cf;
            const float t0 = 1.0f - t1;
            int cfi = (int)cf;        cfi = max(0, min(FID_, cfi));
            int cci = (int)ceilf(_c); cci = max(0, min(FID_, cci));
            const float4 p0 = sP[cfi];
            const float4 p1 = sP[cci];
            float4 v;
            v.x = t1 * p1.x + t0 * p0.x;
            v.y = t1 * p1.y + t0 * p0.y;
            v.z = t1 * p1.z + t0 * p0.z;
            v.w = t1 * p1.w + t0 * p0.w;
            // img[:, xb, yb]: xb indexes dim of size H (stride W), yb the last dim
            red_add_v4(&g_acc[xb * W_ + yb], v);
        }
    }
}

__global__ void finalize_kernel(const float* __restrict__ raw0,
                                float* __restrict__ out) {
    const int p = blockIdx.x * blockDim.x + threadIdx.x;
    const float4 v = g_acc[p];
    out[p + 0 * H_ * W_] = v.x + raw0[p + 0 * H_ * W_];
    out[p + 1 * H_ * W_] = v.y + raw0[p + 1 * H_ * W_];
    out[p + 2 * H_ * W_] = v.z + raw0[p + 2 * H_ * W_];
    out[p + 3 * H_ * W_] = v.w + raw0[p + 3 * H_ * W_];
}

extern "C" void kernel_launch(void* const* d_in, const int* in_sizes, int n_in,
                              void* d_out, int out_size) {
    const float* points = (const float*)d_in[0];
    const int*   choices= (const int*)  d_in[1];
    const float* A      = (const float*)d_in[2];
    const float* b      = (const float*)d_in[3];
    const float* fcol   = (const float*)d_in[4];
    const float* pal    = (const float*)d_in[5];
    const float* minv   = (const float*)d_in[6];
    const float* rngv   = (const float*)d_in[7];
    const float* raw0   = (const float*)d_in[8];
    const int*   skip   = (const int*)  d_in[9];
    float* out = (float*)d_out;

    zero_acc_kernel<<<(H_ * W_) / 256, 256>>>();
    flame_kernel<<<NPTS / 256, 256>>>(points, choices, A, b, fcol, pal,
                                      minv, rngv, skip);
    finalize_kernel<<<(H_ * W_) / 256, 256>>>(raw0, out);
}